// round 5
// baseline (speedup 1.0000x reference)
#include <cuda_runtime.h>
#include <cstdint>
#include <math.h>

#define BATCH 16384
#define DD 4096
#define HH 128
#define EE 64
#define NS 5

typedef unsigned long long ull;

// scratch for h = relu(x@W1+b1): 16384 x 128 fp32 = 8 MB
__device__ float g_h[(size_t)BATCH * HH];

// packed 2-wide fp32 FMA (FFMA2) — bit-identical to 2x fmaf
#define FFMA2(d, a, b) \
    asm("fma.rn.f32x2 %0, %1, %2, %0;" : "+l"(d) : "l"(a), "l"(b))

// ---------------------------------------------------------------------------
// GEMM1: h[B,128] = relu(x[B,4096] @ W1[4096,128] + b1)
// Tile 64m x 128n, BK=32, 256 threads, 8x4 microtile, FFMA2 inner loop.
// As is stored DUPLICATED: As[k][2m]=As[k][2m+1]=x[m][k] so a-operands are
// loadable as packed {a,a} pairs with no packing movs.
// ---------------------------------------------------------------------------
__global__ __launch_bounds__(256) void gemm1_kernel(const float* __restrict__ x,
                                                    const float* __restrict__ W1,
                                                    const float* __restrict__ b1) {
    __shared__ float As[32][132];   // [k][2m], 128 used + pad (row = 528B, 16B-aligned)
    __shared__ float Bs[32][HH];    // [k][n]

    const int tid = threadIdx.x;
    const int tx = tid & 31;   // n/4
    const int ty = tid >> 5;   // m/8
    const int rowBase = blockIdx.x * 64;

    ull acc[8][2];
#pragma unroll
    for (int m = 0; m < 8; m++) { acc[m][0] = 0ull; acc[m][1] = 0ull; }

    const float* xg = x + (size_t)rowBase * DD;

    for (int k0 = 0; k0 < DD; k0 += 32) {
        // load x tile 64x32, transposed + duplicated into As
#pragma unroll
        for (int l = 0; l < 2; l++) {
            int i = tid + 256 * l;          // 0..511
            int r = i >> 3;                 // 0..63
            int kq = (i & 7) * 4;           // 0..28
            float4 v = *(const float4*)(xg + (size_t)r * DD + (k0 + kq));
            float2 d;
            d.x = v.x; d.y = v.x; *(float2*)&As[kq + 0][2 * r] = d;
            d.x = v.y; d.y = v.y; *(float2*)&As[kq + 1][2 * r] = d;
            d.x = v.z; d.y = v.z; *(float2*)&As[kq + 2][2 * r] = d;
            d.x = v.w; d.y = v.w; *(float2*)&As[kq + 3][2 * r] = d;
        }
        // load W1 tile 32x128
#pragma unroll
        for (int l = 0; l < 4; l++) {
            int i = tid + 256 * l;          // 0..1023
            int kr = i >> 5;                // 0..31
            int nc = (i & 31) * 4;          // 0..124
            *(float4*)&Bs[kr][nc] = *(const float4*)(W1 + (size_t)(k0 + kr) * HH + nc);
        }
        __syncthreads();

#pragma unroll
        for (int k = 0; k < 32; k++) {
            // a: 8 duplicated pairs, broadcast within warp (ty uniform)
            const ulonglong2* ap = (const ulonglong2*)&As[k][ty * 16];
            ulonglong2 a01 = ap[0], a23 = ap[1], a45 = ap[2], a67 = ap[3];
            // b: 2 natural pairs
            ulonglong2 bp = *(const ulonglong2*)&Bs[k][tx * 4];
            ull av[8] = {a01.x, a01.y, a23.x, a23.y, a45.x, a45.y, a67.x, a67.y};
#pragma unroll
            for (int m = 0; m < 8; m++) {
                FFMA2(acc[m][0], av[m], bp.x);
                FFMA2(acc[m][1], av[m], bp.y);
            }
        }
        __syncthreads();
    }

    // bias + relu + store
    float4 bv = *(const float4*)&b1[tx * 4];
#pragma unroll
    for (int m = 0; m < 8; m++) {
        int row = rowBase + ty * 8 + m;
        float p0, p1, p2, p3;
        asm("mov.b64 {%0, %1}, %2;" : "=f"(p0), "=f"(p1) : "l"(acc[m][0]));
        asm("mov.b64 {%0, %1}, %2;" : "=f"(p2), "=f"(p3) : "l"(acc[m][1]));
        float4 o;
        o.x = fmaxf(p0 + bv.x, 0.f);
        o.y = fmaxf(p1 + bv.y, 0.f);
        o.z = fmaxf(p2 + bv.z, 0.f);
        o.w = fmaxf(p3 + bv.w, 0.f);
        *(float4*)&g_h[(size_t)row * HH + tx * 4] = o;
    }
}

// ---------------------------------------------------------------------------
// Epilogue: one warp per row; h + packed 5-bit dropout masks broadcast via
// shfl (no per-sample smem rebuild). Lane owns experts 2*lane, 2*lane+1.
// ---------------------------------------------------------------------------
__global__ __launch_bounds__(256) void epilogue_kernel(const float* __restrict__ W2,
                                                       const float* __restrict__ b2,
                                                       const float* __restrict__ m1,
                                                       const float* __restrict__ m2,
                                                       float* __restrict__ out,
                                                       int B) {
    __shared__ float ws2[HH * EE];   // 32 KB

    const int tid = threadIdx.x;
    const int lane = tid & 31;
    const int warp = tid >> 5;

#pragma unroll
    for (int l = 0; l < 8; l++) {
        int i = (tid + 256 * l) * 4;
        *(float4*)&ws2[i] = *(const float4*)&W2[i];
    }
    __syncthreads();

    const int row = blockIdx.x * 8 + warp;
    const float SCALE = 1.4285714285714286f;   // 1/(1-0.3)

    // lane holds 4 scaled h values + packed 5-sample keep masks
    float hv[4];
    {
        float4 h4 = *(const float4*)&g_h[(size_t)row * HH + lane * 4];
        hv[0] = h4.x * SCALE; hv[1] = h4.y * SCALE;
        hv[2] = h4.z * SCALE; hv[3] = h4.w * SCALE;
    }
    int mv[4] = {0, 0, 0, 0};
#pragma unroll
    for (int s = 0; s < NS; s++) {
        float4 u = *(const float4*)&m1[(size_t)s * B * HH + (size_t)row * HH + lane * 4];
        mv[0] |= (u.x >= 0.3f) << s;
        mv[1] |= (u.y >= 0.3f) << s;
        mv[2] |= (u.z >= 0.3f) << s;
        mv[3] |= (u.w >= 0.3f) << s;
    }

    float a0[NS] = {0, 0, 0, 0, 0}, a1[NS] = {0, 0, 0, 0, 0};
    for (int jo = 0; jo < 4; jo++) {
#pragma unroll
        for (int ji = 0; ji < 32; ji++) {
            int j = jo * 32 + ji;
            float hj = __shfl_sync(0xffffffffu, hv[ji & 3], j >> 2);
            int m5   = __shfl_sync(0xffffffffu, mv[ji & 3], j >> 2);
            float2 w = *(float2*)&ws2[j * EE + lane * 2];
#pragma unroll
            for (int s = 0; s < NS; s++) {
                float hjs = (m5 & (1 << s)) ? hj : 0.f;
                a0[s] = fmaf(hjs, w.x, a0[s]);
                a1[s] = fmaf(hjs, w.y, a1[s]);
            }
        }
    }

    float2 b2v = *(const float2*)&b2[lane * 2];
    float lg0[NS], lg1[NS];
    {
        const float* m2r = m2 + (size_t)row * EE + lane * 2;
#pragma unroll
        for (int s = 0; s < NS; s++) {
            float2 mu = *(const float2*)&m2r[(size_t)s * B * EE];
            lg0[s] = (a0[s] + b2v.x) * ((mu.x >= 0.3f) ? SCALE : 0.f);
            lg1[s] = (a1[s] + b2v.y) * ((mu.y >= 0.3f) ? SCALE : 0.f);
        }
    }

    // mean-logits softmax
    float ml0 = (lg0[0] + lg0[1] + lg0[2] + lg0[3] + lg0[4]) * 0.2f;
    float ml1 = (lg1[0] + lg1[1] + lg1[2] + lg1[3] + lg1[4]) * 0.2f;
    float mx = fmaxf(ml0, ml1);
#pragma unroll
    for (int off = 16; off; off >>= 1) mx = fmaxf(mx, __shfl_xor_sync(0xffffffffu, mx, off));
    float p0 = expf(ml0 - mx), p1 = expf(ml1 - mx);
    float sm = p0 + p1;
#pragma unroll
    for (int off = 16; off; off >>= 1) sm += __shfl_xor_sync(0xffffffffu, sm, off);
    float pr0 = p0 / sm, pr1 = p1 / sm;

    // per-sample softmax
    float ap0[NS], ap1[NS];
#pragma unroll
    for (int s = 0; s < NS; s++) {
        float mxs = fmaxf(lg0[s], lg1[s]);
#pragma unroll
        for (int off = 16; off; off >>= 1) mxs = fmaxf(mxs, __shfl_xor_sync(0xffffffffu, mxs, off));
        float e0 = expf(lg0[s] - mxs), e1 = expf(lg1[s] - mxs);
        float ss = e0 + e1;
#pragma unroll
        for (int off = 16; off; off >>= 1) ss += __shfl_xor_sync(0xffffffffu, ss, off);
        ap0[s] = e0 / ss;
        ap1[s] = e1 / ss;
    }

    // std over samples (ddof=1), mean over experts
    float mp0 = (ap0[0] + ap0[1] + ap0[2] + ap0[3] + ap0[4]) * 0.2f;
    float mp1 = (ap1[0] + ap1[1] + ap1[2] + ap1[3] + ap1[4]) * 0.2f;
    float v0 = 0.f, v1 = 0.f;
#pragma unroll
    for (int s = 0; s < NS; s++) {
        float d0 = ap0[s] - mp0, d1 = ap1[s] - mp1;
        v0 = fmaf(d0, d0, v0);
        v1 = fmaf(d1, d1, v1);
    }
    float stds = sqrtf(v0 * 0.25f) + sqrtf(v1 * 0.25f);
#pragma unroll
    for (int off = 16; off; off >>= 1) stds += __shfl_xor_sync(0xffffffffu, stds, off);
    float unc = stds / 64.0f;

    // top-4, jax tie-break (equal -> lower index)
    float q0 = pr0, q1 = pr1;
    const int i0 = lane * 2, i1 = lane * 2 + 1;
    float fp[4];
    int fi[4];
#pragma unroll
    for (int k = 0; k < 4; k++) {
        float bp;
        int bi;
        if (q0 >= q1) { bp = q0; bi = i0; }
        else          { bp = q1; bi = i1; }
#pragma unroll
        for (int off = 16; off; off >>= 1) {
            float op = __shfl_xor_sync(0xffffffffu, bp, off);
            int oi = __shfl_xor_sync(0xffffffffu, bi, off);
            if (op > bp || (op == bp && oi < bi)) { bp = op; bi = oi; }
        }
        fp[k] = bp;
        fi[k] = bi;
        if (bi == i0) q0 = -1.f;
        if (bi == i1) q1 = -1.f;
    }

    if (lane == 0) {
        bool uncertain = unc > 0.3f;
        size_t pb = (size_t)4 * B;
        size_t ub = (size_t)8 * B;
        out[(size_t)row * 4 + 0] = (float)fi[0];
        out[(size_t)row * 4 + 1] = (float)fi[1];
        out[(size_t)row * 4 + 2] = uncertain ? (float)fi[2] : -1.0f;
        out[(size_t)row * 4 + 3] = uncertain ? (float)fi[3] : -1.0f;
        out[pb + (size_t)row * 4 + 0] = fp[0];
        out[pb + (size_t)row * 4 + 1] = fp[1];
        out[pb + (size_t)row * 4 + 2] = uncertain ? fp[2] : 0.0f;
        out[pb + (size_t)row * 4 + 3] = uncertain ? fp[3] : 0.0f;
        out[ub + row] = unc;
    }
}

extern "C" void kernel_launch(void* const* d_in, const int* in_sizes, int n_in,
                              void* d_out, int out_size) {
    const float* x  = (const float*)d_in[0];
    const float* W1 = (const float*)d_in[1];
    const float* b1 = (const float*)d_in[2];
    const float* W2 = (const float*)d_in[3];
    const float* b2 = (const float*)d_in[4];
    const float* m1 = (const float*)d_in[5];
    const float* m2 = (const float*)d_in[6];
    float* out = (float*)d_out;

    int B = in_sizes[0] / DD;   // 16384

    gemm1_kernel<<<B / 64, 256>>>(x, W1, b1);
    epilogue_kernel<<<B / 8, 256>>>(W2, b2, m1, m2, out, B);
}

// round 6
// speedup vs baseline: 1.6383x; 1.6383x over previous
#include <cuda_runtime.h>
#include <cstdint>
#include <math.h>

#define BATCH 16384
#define DD 4096
#define HH 128
#define EE 64
#define NS 5

#define BM 128
#define BK 32
#define NITER (DD / BK)

// smem strides in floats (padded for conflict-free fragment loads)
#define ASTRIDE 36     // 32 + 4 pad  (row = 144B, 16B aligned)
#define BSTRIDE 136    // 128 + 8 pad (row = 544B, 16B aligned)
#define ASZ (BM * ASTRIDE)            // 4608 floats
#define BSZ (BK * BSTRIDE)            // 4352 floats
#define STAGE (ASZ + BSZ)             // 8960 floats
#define SMEM_BYTES (2 * STAGE * 4)    // 71680 B

__device__ float g_h[(size_t)BATCH * HH];   // h scratch, 8 MB

__device__ __forceinline__ uint32_t smem_u32(const void* p) {
    uint32_t a;
    asm("{ .reg .u64 t; cvta.to.shared.u64 t, %1; cvt.u32.u64 %0, t; }" : "=r"(a) : "l"(p));
    return a;
}
__device__ __forceinline__ void cp16(uint32_t dst, const void* src) {
    asm volatile("cp.async.cg.shared.global [%0], [%1], 16;" :: "r"(dst), "l"(src));
}
#define CP_COMMIT() asm volatile("cp.async.commit_group;" ::: "memory")
#define CP_WAIT1()  asm volatile("cp.async.wait_group 1;" ::: "memory")
#define CP_WAIT0()  asm volatile("cp.async.wait_group 0;" ::: "memory")

__device__ __forceinline__ void mma8(float* c, const uint32_t* a, const uint32_t* b) {
    asm volatile(
        "mma.sync.aligned.m16n8k8.row.col.f32.tf32.tf32.f32 "
        "{%0,%1,%2,%3}, {%4,%5,%6,%7}, {%8,%9}, {%0,%1,%2,%3};"
        : "+f"(c[0]), "+f"(c[1]), "+f"(c[2]), "+f"(c[3])
        : "r"(a[0]), "r"(a[1]), "r"(a[2]), "r"(a[3]), "r"(b[0]), "r"(b[1]));
}
__device__ __forceinline__ void split_tf32(float v, uint32_t& hi, uint32_t& lo) {
    uint32_t h = __float_as_uint(v) & 0xFFFFE000u;   // exact tf32 high part
    hi = h;
    float l = v - __uint_as_float(h);                // exact residual
    asm("cvt.rna.tf32.f32 %0, %1;" : "=r"(lo) : "f"(l));
}

// ---------------------------------------------------------------------------
// GEMM1: h = relu(x @ W1 + b1) via mma.sync tf32, 3-pass exact split.
// CTA: 128x128, BK=32, 8 warps (4m x 2n), warp tile 32x64.
// ---------------------------------------------------------------------------
__device__ __forceinline__ void load_tile(uint32_t smb, int s, int it, int tid,
                                          int rowBase,
                                          const float* __restrict__ x,
                                          const float* __restrict__ W1) {
    int k0 = it * BK;
    uint32_t aB = smb + (uint32_t)(s * STAGE * 4);
    uint32_t bB = aB + ASZ * 4;
#pragma unroll
    for (int l = 0; l < 4; l++) {
        int c = tid + 256 * l;          // 0..1023
        int r = c >> 3, q = c & 7;      // row 0..127, quad 0..7
        cp16(aB + r * (ASTRIDE * 4) + q * 16,
             x + (size_t)(rowBase + r) * DD + k0 + q * 4);
    }
#pragma unroll
    for (int l = 0; l < 4; l++) {
        int c = tid + 256 * l;
        int k = c >> 5, nq = c & 31;    // k 0..31, nquad 0..31
        cp16(bB + k * (BSTRIDE * 4) + nq * 16,
             W1 + (size_t)(k0 + k) * HH + nq * 4);
    }
}

__global__ __launch_bounds__(256, 1) void gemm1_mma(const float* __restrict__ x,
                                                    const float* __restrict__ W1,
                                                    const float* __restrict__ b1) {
    extern __shared__ float sm[];
    const int tid = threadIdx.x;
    const int lane = tid & 31;
    const int wid = tid >> 5;
    const int wm = wid & 3;        // m block: 32*wm
    const int wn = wid >> 2;       // n block: 64*wn
    const int g = lane >> 2, t = lane & 3;
    const int rowBase = blockIdx.x * BM;
    const uint32_t smb = smem_u32(sm);

    float acc[2][8][4];
#pragma unroll
    for (int i = 0; i < 2; i++)
#pragma unroll
        for (int j = 0; j < 8; j++)
#pragma unroll
            for (int r = 0; r < 4; r++) acc[i][j][r] = 0.f;

    load_tile(smb, 0, 0, tid, rowBase, x, W1);
    CP_COMMIT();

    for (int it = 0; it < NITER; ++it) {
        const int s = it & 1;
        if (it + 1 < NITER) {
            load_tile(smb, s ^ 1, it + 1, tid, rowBase, x, W1);
            CP_COMMIT();
            CP_WAIT1();
        } else {
            CP_WAIT0();
        }
        __syncthreads();

        const float* As = sm + s * STAGE;
        const float* Bs = As + ASZ;
#pragma unroll
        for (int ks = 0; ks < 4; ks++) {
            const int kb = ks * 8;
            uint32_t aHi[2][4], aLo[2][4];
#pragma unroll
            for (int i = 0; i < 2; i++) {
                const float* ap = As + (size_t)(wm * 32 + i * 16 + g) * ASTRIDE + kb + t;
                split_tf32(ap[0],               aHi[i][0], aLo[i][0]);
                split_tf32(ap[8 * ASTRIDE],     aHi[i][1], aLo[i][1]);
                split_tf32(ap[4],               aHi[i][2], aLo[i][2]);
                split_tf32(ap[8 * ASTRIDE + 4], aHi[i][3], aLo[i][3]);
            }
            uint32_t bHi[8][2], bLo[8][2];
#pragma unroll
            for (int j = 0; j < 8; j++) {
                const float* bp = Bs + (size_t)(kb + t) * BSTRIDE + wn * 64 + j * 8 + g;
                split_tf32(bp[0],               bHi[j][0], bLo[j][0]);
                split_tf32(bp[4 * BSTRIDE],     bHi[j][1], bLo[j][1]);
            }
#pragma unroll
            for (int i = 0; i < 2; i++)
#pragma unroll
                for (int j = 0; j < 8; j++) {
                    mma8(acc[i][j], aHi[i], bHi[j]);
                    mma8(acc[i][j], aHi[i], bLo[j]);
                    mma8(acc[i][j], aLo[i], bHi[j]);
                }
        }
        __syncthreads();
    }

    // bias + relu + store
#pragma unroll
    for (int i = 0; i < 2; i++) {
        int r0 = rowBase + wm * 32 + i * 16 + g;
#pragma unroll
        for (int j = 0; j < 8; j++) {
            int col = wn * 64 + j * 8 + 2 * t;
            float2 bv = *(const float2*)&b1[col];
            float2 o0, o1;
            o0.x = fmaxf(acc[i][j][0] + bv.x, 0.f);
            o0.y = fmaxf(acc[i][j][1] + bv.y, 0.f);
            o1.x = fmaxf(acc[i][j][2] + bv.x, 0.f);
            o1.y = fmaxf(acc[i][j][3] + bv.y, 0.f);
            *(float2*)&g_h[(size_t)r0 * HH + col] = o0;
            *(float2*)&g_h[(size_t)(r0 + 8) * HH + col] = o1;
        }
    }
}

// ---------------------------------------------------------------------------
// Epilogue: one warp per row; h + packed 5-bit dropout masks broadcast via
// shfl. Lane owns experts 2*lane, 2*lane+1. (unchanged from R5: 66 us)
// ---------------------------------------------------------------------------
__global__ __launch_bounds__(256) void epilogue_kernel(const float* __restrict__ W2,
                                                       const float* __restrict__ b2,
                                                       const float* __restrict__ m1,
                                                       const float* __restrict__ m2,
                                                       float* __restrict__ out,
                                                       int B) {
    __shared__ float ws2[HH * EE];   // 32 KB

    const int tid = threadIdx.x;
    const int lane = tid & 31;
    const int warp = tid >> 5;

#pragma unroll
    for (int l = 0; l < 8; l++) {
        int i = (tid + 256 * l) * 4;
        *(float4*)&ws2[i] = *(const float4*)&W2[i];
    }
    __syncthreads();

    const int row = blockIdx.x * 8 + warp;
    const float SCALE = 1.4285714285714286f;   // 1/(1-0.3)

    float hv[4];
    {
        float4 h4 = *(const float4*)&g_h[(size_t)row * HH + lane * 4];
        hv[0] = h4.x * SCALE; hv[1] = h4.y * SCALE;
        hv[2] = h4.z * SCALE; hv[3] = h4.w * SCALE;
    }
    int mv[4] = {0, 0, 0, 0};
#pragma unroll
    for (int s = 0; s < NS; s++) {
        float4 u = *(const float4*)&m1[(size_t)s * B * HH + (size_t)row * HH + lane * 4];
        mv[0] |= (u.x >= 0.3f) << s;
        mv[1] |= (u.y >= 0.3f) << s;
        mv[2] |= (u.z >= 0.3f) << s;
        mv[3] |= (u.w >= 0.3f) << s;
    }

    float a0[NS] = {0, 0, 0, 0, 0}, a1[NS] = {0, 0, 0, 0, 0};
    for (int jo = 0; jo < 4; jo++) {
#pragma unroll
        for (int ji = 0; ji < 32; ji++) {
            int j = jo * 32 + ji;
            float hj = __shfl_sync(0xffffffffu, hv[ji & 3], j >> 2);
            int m5   = __shfl_sync(0xffffffffu, mv[ji & 3], j >> 2);
            float2 w = *(float2*)&ws2[j * EE + lane * 2];
#pragma unroll
            for (int s = 0; s < NS; s++) {
                float hjs = (m5 & (1 << s)) ? hj : 0.f;
                a0[s] = fmaf(hjs, w.x, a0[s]);
                a1[s] = fmaf(hjs, w.y, a1[s]);
            }
        }
    }

    float2 b2v = *(const float2*)&b2[lane * 2];
    float lg0[NS], lg1[NS];
    {
        const float* m2r = m2 + (size_t)row * EE + lane * 2;
#pragma unroll
        for (int s = 0; s < NS; s++) {
            float2 mu = *(const float2*)&m2r[(size_t)s * B * EE];
            lg0[s] = (a0[s] + b2v.x) * ((mu.x >= 0.3f) ? SCALE : 0.f);
            lg1[s] = (a1[s] + b2v.y) * ((mu.y >= 0.3f) ? SCALE : 0.f);
        }
    }

    float ml0 = (lg0[0] + lg0[1] + lg0[2] + lg0[3] + lg0[4]) * 0.2f;
    float ml1 = (lg1[0] + lg1[1] + lg1[2] + lg1[3] + lg1[4]) * 0.2f;
    float mx = fmaxf(ml0, ml1);
#pragma unroll
    for (int off = 16; off; off >>= 1) mx = fmaxf(mx, __shfl_xor_sync(0xffffffffu, mx, off));
    float p0 = expf(ml0 - mx), p1 = expf(ml1 - mx);
    float sm = p0 + p1;
#pragma unroll
    for (int off = 16; off; off >>= 1) sm += __shfl_xor_sync(0xffffffffu, sm, off);
    float pr0 = p0 / sm, pr1 = p1 / sm;

    float ap0[NS], ap1[NS];
#pragma unroll
    for (int s = 0; s < NS; s++) {
        float mxs = fmaxf(lg0[s], lg1[s]);
#pragma unroll
        for (int off = 16; off; off >>= 1) mxs = fmaxf(mxs, __shfl_xor_sync(0xffffffffu, mxs, off));
        float e0 = expf(lg0[s] - mxs), e1 = expf(lg1[s] - mxs);
        float ss = e0 + e1;
#pragma unroll
        for (int off = 16; off; off >>= 1) ss += __shfl_xor_sync(0xffffffffu, ss, off);
        ap0[s] = e0 / ss;
        ap1[s] = e1 / ss;
    }

    float mp0 = (ap0[0] + ap0[1] + ap0[2] + ap0[3] + ap0[4]) * 0.2f;
    float mp1 = (ap1[0] + ap1[1] + ap1[2] + ap1[3] + ap1[4]) * 0.2f;
    float v0 = 0.f, v1 = 0.f;
#pragma unroll
    for (int s = 0; s < NS; s++) {
        float d0 = ap0[s] - mp0, d1 = ap1[s] - mp1;
        v0 = fmaf(d0, d0, v0);
        v1 = fmaf(d1, d1, v1);
    }
    float stds = sqrtf(v0 * 0.25f) + sqrtf(v1 * 0.25f);
#pragma unroll
    for (int off = 16; off; off >>= 1) stds += __shfl_xor_sync(0xffffffffu, stds, off);
    float unc = stds / 64.0f;

    float q0 = pr0, q1 = pr1;
    const int i0 = lane * 2, i1 = lane * 2 + 1;
    float fp[4];
    int fi[4];
#pragma unroll
    for (int k = 0; k < 4; k++) {
        float bp;
        int bi;
        if (q0 >= q1) { bp = q0; bi = i0; }
        else          { bp = q1; bi = i1; }
#pragma unroll
        for (int off = 16; off; off >>= 1) {
            float op = __shfl_xor_sync(0xffffffffu, bp, off);
            int oi = __shfl_xor_sync(0xffffffffu, bi, off);
            if (op > bp || (op == bp && oi < bi)) { bp = op; bi = oi; }
        }
        fp[k] = bp;
        fi[k] = bi;
        if (bi == i0) q0 = -1.f;
        if (bi == i1) q1 = -1.f;
    }

    if (lane == 0) {
        bool uncertain = unc > 0.3f;
        size_t pb = (size_t)4 * B;
        size_t ub = (size_t)8 * B;
        out[(size_t)row * 4 + 0] = (float)fi[0];
        out[(size_t)row * 4 + 1] = (float)fi[1];
        out[(size_t)row * 4 + 2] = uncertain ? (float)fi[2] : -1.0f;
        out[(size_t)row * 4 + 3] = uncertain ? (float)fi[3] : -1.0f;
        out[pb + (size_t)row * 4 + 0] = fp[0];
        out[pb + (size_t)row * 4 + 1] = fp[1];
        out[pb + (size_t)row * 4 + 2] = uncertain ? fp[2] : 0.0f;
        out[pb + (size_t)row * 4 + 3] = uncertain ? fp[3] : 0.0f;
        out[ub + row] = unc;
    }
}

extern "C" void kernel_launch(void* const* d_in, const int* in_sizes, int n_in,
                              void* d_out, int out_size) {
    const float* x  = (const float*)d_in[0];
    const float* W1 = (const float*)d_in[1];
    const float* b1 = (const float*)d_in[2];
    const float* W2 = (const float*)d_in[3];
    const float* b2 = (const float*)d_in[4];
    const float* m1 = (const float*)d_in[5];
    const float* m2 = (const float*)d_in[6];
    float* out = (float*)d_out;

    int B = in_sizes[0] / DD;   // 16384

    cudaFuncSetAttribute(gemm1_mma, cudaFuncAttributeMaxDynamicSharedMemorySize, SMEM_BYTES);

    gemm1_mma<<<B / BM, 256, SMEM_BYTES>>>(x, W1, b1);
    epilogue_kernel<<<B / 8, 256>>>(W2, b2, m1, m2, out, B);
}